// round 16
// baseline (speedup 1.0000x reference)
#include <cuda_runtime.h>
#include <math.h>

// ---------------- problem constants ----------------
#define NPTS   8192
#define FIN    16
#define HID    64
#define CUTS   8
#define NBLK   64           // queries per conv CTA
#define SPLIT  64           // split of the source-point dimension across CTAs
#define CHUNK  (NPTS/SPLIT) // 128 source points per CTA (= one TILE)
#define TILE   128          // staged source-point tile
#define GROUPS 4
#define INV_GN (1.0f/(float)(NPTS*(HID/GROUPS)))   // 1/131072
#define PSCALE 0.07856742013183862f                // 1/(sqrt(2)*9)

typedef unsigned long long u64t;

// ---------------- scratch (no allocations allowed) ----------------
__device__ float g_f[NPTS*HID];                    // input features; reused for reduced conv sums
__device__ float g_pre[NPTS*HID];                  // pre-GroupNorm buffer (both MLP stages)
__device__ float g_partial[SPLIT][NPTS][HID];      // conv partial sums (128 MB)
__device__ float g_statp_in[128][8];               // per-CTA group stats (sum[4], sumsq[4])
__device__ float g_statp_out[128][8];

// ---------------- f32x2 helpers (sm_100+ packed fp32) ----------------
__device__ __forceinline__ u64t fma2(u64t a, u64t b, u64t c) {
    u64t d; asm("fma.rn.f32x2 %0, %1, %2, %3;" : "=l"(d) : "l"(a), "l"(b), "l"(c)); return d;
}
__device__ __forceinline__ u64t mul2(u64t a, u64t b) {
    u64t d; asm("mul.rn.f32x2 %0, %1, %2;" : "=l"(d) : "l"(a), "l"(b)); return d;
}
__device__ __forceinline__ u64t bc2(float x) {
    u64t d; asm("mov.b64 %0, {%1, %1};" : "=l"(d) : "f"(x)); return d;
}
__device__ __forceinline__ u64t pk2(float x, float y) {
    u64t d; asm("mov.b64 %0, {%1, %2};" : "=l"(d) : "f"(x), "f"(y)); return d;
}
__device__ __forceinline__ float2 up2(u64t d) {
    float2 r; asm("mov.b64 {%0, %1}, %2;" : "=f"(r.x), "=f"(r.y) : "l"(d)); return r;
}
__device__ __forceinline__ u64t relu2(u64t s) {
    float2 g = up2(s);
    return pk2(fmaxf(g.x, 0.f), fmaxf(g.y, 0.f));
}
__device__ __forceinline__ float leaky(float x) { return x >= 0.f ? x : 0.2f*x; }

// =====================================================================
// Position 0: zero the (now 128-row) stat arrays; keeps ncu slot on conv.
// =====================================================================
__global__ void zero_stats_kernel() {
    int i = threadIdx.x;
    if (i < 128) {
        #pragma unroll
        for (int j = 0; j < 8; j++) { g_statp_in[i][j] = 0.f; g_statp_out[i][j] = 0.f; }
    }
}

// =====================================================================
// Input MLP, channel-split: 128 CTAs. CTA = (point-block pb, half cb).
// Duplicates the cheap 16->64 layer, computes 32 output channels of
// layer 2 (= GroupNorm groups {2cb, 2cb+1} exactly). Stats per CTA.
// =====================================================================
__global__ __launch_bounds__(128) void mlp_in_kernel(
    const float* __restrict__ feat,
    const float* __restrict__ W1, const float* __restrict__ b1,
    const float* __restrict__ W2, const float* __restrict__ b2)
{
    __shared__ __align__(16) float sW1[HID*FIN];
    __shared__ __align__(16) float sW2h[32*HID];
    __shared__ float sb1[HID], sb2h[32];
    __shared__ float red[128][4];

    const int tid = threadIdx.x;
    const int pb = blockIdx.x >> 1, cb = blockIdx.x & 1;

    for (int i = tid; i < HID*FIN; i += 128) sW1[i] = W1[i];
    for (int i = tid; i < 32*HID; i += 128) sW2h[i] = W2[cb*32*HID + i];
    if (tid < HID) sb1[tid] = b1[tid];
    if (tid < 32) sb2h[tid] = b2[cb*32 + tid];
    __syncthreads();

    const int p = pb*128 + tid;
    float x[FIN];
    #pragma unroll
    for (int k = 0; k < FIN/4; k++) {
        float4 v = ((const float4*)(feat + (size_t)p*FIN))[k];
        x[4*k]=v.x; x[4*k+1]=v.y; x[4*k+2]=v.z; x[4*k+3]=v.w;
    }
    float h[HID];
    for (int hh = 0; hh < HID; ++hh) {
        float a = sb1[hh];
        const float4* wr = (const float4*)&sW1[hh*FIN];
        #pragma unroll
        for (int c4 = 0; c4 < FIN/4; c4++) {
            float4 wv = wr[c4];
            a = fmaf(wv.x, x[4*c4], a);   a = fmaf(wv.y, x[4*c4+1], a);
            a = fmaf(wv.z, x[4*c4+2], a); a = fmaf(wv.w, x[4*c4+3], a);
        }
        h[hh] = leaky(a);
    }
    float y[32];
    for (int hh = 0; hh < 32; ++hh) {
        float a = sb2h[hh];
        const float4* wr = (const float4*)&sW2h[hh*HID];
        #pragma unroll
        for (int c4 = 0; c4 < HID/4; c4++) {
            float4 wv = wr[c4];
            a = fmaf(wv.x, h[4*c4], a);   a = fmaf(wv.y, h[4*c4+1], a);
            a = fmaf(wv.z, h[4*c4+2], a); a = fmaf(wv.w, h[4*c4+3], a);
        }
        y[hh] = leaky(a);
    }
    #pragma unroll
    for (int k = 0; k < 8; k++)
        ((float4*)(g_pre + (size_t)p*HID + cb*32))[k] = make_float4(y[4*k], y[4*k+1], y[4*k+2], y[4*k+3]);

    float sums[2] = {0,0}, sqs[2] = {0,0};
    #pragma unroll
    for (int hh = 0; hh < 32; ++hh) { int gI = hh >> 4; sums[gI] += y[hh]; sqs[gI] += y[hh]*y[hh]; }
    red[tid][0] = sums[0]; red[tid][1] = sums[1];
    red[tid][2] = sqs[0];  red[tid][3] = sqs[1];
    __syncthreads();
    for (int st = 64; st > 0; st >>= 1) {
        if (tid < st) {
            #pragma unroll
            for (int j = 0; j < 4; j++) red[tid][j] += red[tid+st][j];
        }
        __syncthreads();
    }
    if (tid == 0) {
        g_statp_in[blockIdx.x][cb*2+0] = red[0][0];
        g_statp_in[blockIdx.x][cb*2+1] = red[0][1];
        g_statp_in[blockIdx.x][4+cb*2+0] = red[0][2];
        g_statp_in[blockIdx.x][4+cb*2+1] = red[0][3];
    }
}

// =====================================================================
// GroupNorm finalize: 128 CTAs x 64 threads. stage 0 -> g_f, 1 -> d_out
// =====================================================================
__global__ __launch_bounds__(64) void norm_kernel(int stage,
    const float* __restrict__ gamma, const float* __restrict__ beta,
    float* __restrict__ dout)
{
    __shared__ float st[8];
    __shared__ float sg[HID], sb[HID];
    const int tid = threadIdx.x;
    const float (*statp)[8] = (stage == 0) ? g_statp_in : g_statp_out;
    float* out = (stage == 0) ? g_f : dout;

    if (tid < 8) {
        float s = 0.f;
        for (int j = 0; j < 128; j++) s += statp[j][tid];
        st[tid] = s;
    }
    sg[tid] = gamma[tid]; sb[tid] = beta[tid];
    __syncthreads();

    float m[GROUPS], scl[GROUPS];
    #pragma unroll
    for (int gI = 0; gI < GROUPS; gI++) {
        float mm = st[gI] * INV_GN;
        float vv = st[4+gI] * INV_GN - mm*mm;
        m[gI] = mm; scl[gI] = rsqrtf(vv + 1e-5f);
    }
    const int p = blockIdx.x*64 + tid;
    #pragma unroll
    for (int hh = 0; hh < HID; ++hh) {
        int gI = hh >> 4;
        out[(size_t)p*HID + hh] = (g_pre[(size_t)p*HID + hh] - m[gI])*scl[gI]*sg[hh] + sb[hh];
    }
}

// =====================================================================
// All-pairs conv. CTA = 128 threads = 64 queries x 2 channel-halves.
// Each thread: 1 query, 32 channels (16 f32x2 accumulators).
// t2 x4 unroll; launch_bounds(128,3); SPLIT=64 — R15-proven optimum.
// =====================================================================
__global__ __launch_bounds__(128, 3) void conv_kernel(
    const float* __restrict__ points, const float* __restrict__ nuv,
    const float* __restrict__ A1, const float* __restrict__ B1,
    const float* __restrict__ A2, const float* __restrict__ B2)
{
    __shared__ __align__(16) float4 s_pt[TILE];     // x,y,z (scaled), |p|^2
    __shared__ __align__(16) float4 s_nm[TILE];     // normal row 0
    __shared__ __align__(16) float  s_f[TILE][HID];
    __shared__ __align__(16) u64t   s_a2[32][8];    // [h-pair][cut] packed {A2[2hp][c], A2[2hp+1][c]}
    __shared__ __align__(16) u64t   s_b2[32];
    __shared__ __align__(16) float4 s_a1[CUTS];     // {a0, a1, a2, B1c}

    const int tid  = threadIdx.x;
    const int qi   = tid & 63;
    const int half = tid >> 6;                      // 0: channels 0..31, 1: 32..63
    const int q    = blockIdx.x * NBLK + qi;

    // per-query invariants (registers)
    const float qx = points[3*q+0]*PSCALE, qy = points[3*q+1]*PSCALE, qz = points[3*q+2]*PSCALE;
    const float qn2 = qx*qx + qy*qy + qz*qz;
    const float u00 = nuv[9*q+0], u01 = nuv[9*q+1], u02 = nuv[9*q+2];
    const float u10 = nuv[9*q+3], u11 = nuv[9*q+4], u12 = nuv[9*q+5];
    const float u20 = nuv[9*q+6], u21 = nuv[9*q+7], u22 = nuv[9*q+8];

    // stage A1/B1 (broadcast-friendly), packed A2/B2
    if (tid < CUTS) s_a1[tid] = make_float4(A1[3*tid+0], A1[3*tid+1], A1[3*tid+2], B1[tid]);
    for (int i = tid; i < 32*8; i += 128) {
        int hp = i >> 3, c = i & 7;
        s_a2[hp][c] = pk2(A2[(2*hp)*CUTS + c], A2[(2*hp+1)*CUTS + c]);
    }
    if (tid < 32) s_b2[tid] = pk2(B2[2*tid], B2[2*tid+1]);

    u64t acc[16];
    #pragma unroll
    for (int i = 0; i < 16; i++) acc[i] = 0ull;

    const u64t (*a2h)[8] = (const u64t (*)[8])&s_a2[half*16];
    const ulonglong2* b2h = (const ulonglong2*)&s_b2[half*16];

    const int n0 = blockIdx.y * CHUNK;
    for (int t = 0; t < CHUNK; t += TILE) {
        __syncthreads();
        {
            int n = n0 + t + tid;
            float px = points[3*n]*PSCALE, py = points[3*n+1]*PSCALE, pz = points[3*n+2]*PSCALE;
            s_pt[tid] = make_float4(px, py, pz, px*px + py*py + pz*pz);
            s_nm[tid] = make_float4(nuv[9*n], nuv[9*n+1], nuv[9*n+2], 0.f);
        }
        for (int i = tid; i < TILE*(HID/4); i += 128) {
            int r = i >> 4, c4 = i & 15;
            ((float4*)s_f[r])[c4] = ((const float4*)(g_f + (size_t)(n0+t+r)*HID))[c4];
        }
        __syncthreads();

        #pragma unroll 1
        for (int t2 = 0; t2 < TILE; t2 += 4) {
            // ---- prologue: window + local coords for 4 source points ----
            float X[4][3];
            u64t wp[4];
            #pragma unroll
            for (int pp = 0; pp < 4; ++pp) {
                float4 p = s_pt[t2+pp];
                float4 m = s_nm[t2+pp];
                float dn = fmaf(u00, m.x, fmaf(u01, m.y, u02*m.z));
                float tt = 2.f - dn;
                float pd = fmaf(qx, p.x, fmaf(qy, p.y, qz*p.z));
                float d2 = fmaf(-2.f, pd, p.w + qn2);
                wp[pp] = bc2(__expf(-(d2*tt*tt)));
                float dx = p.x - qx, dy = p.y - qy, dz = p.z - qz;
                X[pp][0] = fmaf(u00,dx, fmaf(u01,dy, u02*dz));
                X[pp][1] = fmaf(u10,dx, fmaf(u11,dy, u12*dz));
                X[pp][2] = fmaf(u20,dx, fmaf(u21,dy, u22*dz));
            }
            // ---- cut activations (A1 broadcast; each row loaded once) ----
            u64t hb[4][CUTS];
            #pragma unroll
            for (int c = 0; c < CUTS; ++c) {
                float4 a = s_a1[c];
                #pragma unroll
                for (int pp = 0; pp < 4; ++pp) {
                    float h = fmaf(a.x, X[pp][0], fmaf(a.y, X[pp][1], fmaf(a.z, X[pp][2], a.w)));
                    hb[pp][c] = bc2(fmaxf(h, 0.f));
                }
            }

            #pragma unroll
            for (int hp2 = 0; hp2 < 8; ++hp2) {
                ulonglong2 bb = b2h[hp2];
                u64t sA0 = bb.x, sA1 = bb.x, sA2v = bb.x, sA3 = bb.x;
                u64t sB0 = bb.y, sB1 = bb.y, sB2v = bb.y, sB3 = bb.y;
                const ulonglong2* a0p = (const ulonglong2*)a2h[2*hp2];
                const ulonglong2* a1p = (const ulonglong2*)a2h[2*hp2+1];
                #pragma unroll
                for (int k = 0; k < 4; ++k) {
                    ulonglong2 A = a0p[k];
                    sA0 = fma2(A.x, hb[0][2*k], sA0); sA0 = fma2(A.y, hb[0][2*k+1], sA0);
                    sA1 = fma2(A.x, hb[1][2*k], sA1); sA1 = fma2(A.y, hb[1][2*k+1], sA1);
                    sA2v= fma2(A.x, hb[2][2*k], sA2v);sA2v= fma2(A.y, hb[2][2*k+1], sA2v);
                    sA3 = fma2(A.x, hb[3][2*k], sA3); sA3 = fma2(A.y, hb[3][2*k+1], sA3);
                    ulonglong2 B = a1p[k];
                    sB0 = fma2(B.x, hb[0][2*k], sB0); sB0 = fma2(B.y, hb[0][2*k+1], sB0);
                    sB1 = fma2(B.x, hb[1][2*k], sB1); sB1 = fma2(B.y, hb[1][2*k+1], sB1);
                    sB2v= fma2(B.x, hb[2][2*k], sB2v);sB2v= fma2(B.y, hb[2][2*k+1], sB2v);
                    sB3 = fma2(B.x, hb[3][2*k], sB3); sB3 = fma2(B.y, hb[3][2*k+1], sB3);
                }
                u64t aA = acc[2*hp2], aB = acc[2*hp2+1];
                {
                    ulonglong2 ff = ((const ulonglong2*)&s_f[t2+0][half*32])[hp2];
                    aA = fma2(mul2(relu2(sA0), wp[0]), ff.x, aA);
                    aB = fma2(mul2(relu2(sB0), wp[0]), ff.y, aB);
                }
                {
                    ulonglong2 ff = ((const ulonglong2*)&s_f[t2+1][half*32])[hp2];
                    aA = fma2(mul2(relu2(sA1), wp[1]), ff.x, aA);
                    aB = fma2(mul2(relu2(sB1), wp[1]), ff.y, aB);
                }
                {
                    ulonglong2 ff = ((const ulonglong2*)&s_f[t2+2][half*32])[hp2];
                    aA = fma2(mul2(relu2(sA2v), wp[2]), ff.x, aA);
                    aB = fma2(mul2(relu2(sB2v), wp[2]), ff.y, aB);
                }
                {
                    ulonglong2 ff = ((const ulonglong2*)&s_f[t2+3][half*32])[hp2];
                    aA = fma2(mul2(relu2(sA3), wp[3]), ff.x, aA);
                    aB = fma2(mul2(relu2(sB3), wp[3]), ff.y, aB);
                }
                acc[2*hp2] = aA; acc[2*hp2+1] = aB;
            }
        }
    }

    float* outp = &g_partial[blockIdx.y][q][half*32];
    #pragma unroll
    for (int hp = 0; hp < 8; ++hp) {
        float2 v0 = up2(acc[2*hp]);
        float2 v1 = up2(acc[2*hp+1]);
        ((float4*)outp)[hp] = make_float4(v0.x, v0.y, v1.x, v1.y);
    }
}

// =====================================================================
// Partial reduction: one thread per (point, channel-pair), 4 chains.
// Result overwrites g_f. 128 MB read, fully coalesced.
// =====================================================================
__global__ __launch_bounds__(256) void reduce_kernel() {
    const int idx = blockIdx.x*256 + threadIdx.x;   // 0 .. NPTS*32-1
    const int p  = idx >> 5;
    const int pr = idx & 31;
    const size_t stride = (size_t)NPTS * HID / 2;   // float2 units between splits
    const float2* src = (const float2*)&g_partial[0][p][2*pr];

    float2 a0 = make_float2(0.f, 0.f), a1 = a0, a2 = a0, a3 = a0;
    #pragma unroll 4
    for (int sp = 0; sp < SPLIT; sp += 4) {
        float2 v0 = src[(sp+0)*stride];
        float2 v1 = src[(sp+1)*stride];
        float2 v2 = src[(sp+2)*stride];
        float2 v3 = src[(sp+3)*stride];
        a0.x += v0.x; a0.y += v0.y;
        a1.x += v1.x; a1.y += v1.y;
        a2.x += v2.x; a2.y += v2.y;
        a3.x += v3.x; a3.y += v3.y;
    }
    float2 r;
    r.x = (a0.x + a1.x) + (a2.x + a3.x);
    r.y = (a0.y + a1.y) + (a2.y + a3.y);
    ((float2*)g_f)[idx] = r;
}

// =====================================================================
// Output MLP, channel-split: 128 CTAs = (point-block, half). Reads the
// reduced conv sums from g_f; duplicates layer 1, splits layer 2.
// =====================================================================
__global__ __launch_bounds__(128) void mlp_out_kernel(
    const float* __restrict__ W1, const float* __restrict__ b1,
    const float* __restrict__ W2, const float* __restrict__ b2)
{
    __shared__ __align__(16) float sW1[HID*HID];
    __shared__ __align__(16) float sW2h[32*HID];
    __shared__ float sb1[HID], sb2h[32];
    __shared__ float red[128][4];

    const int tid = threadIdx.x;
    const int pb = blockIdx.x >> 1, cb = blockIdx.x & 1;

    for (int i = tid; i < HID*HID; i += 128) sW1[i] = W1[i];
    for (int i = tid; i < 32*HID; i += 128) sW2h[i] = W2[cb*32*HID + i];
    if (tid < HID) sb1[tid] = b1[tid];
    if (tid < 32) sb2h[tid] = b2[cb*32 + tid];
    __syncthreads();

    const int p = pb*128 + tid;
    float x[HID];
    #pragma unroll
    for (int k = 0; k < HID/4; k++) {
        float4 v = ((const float4*)(g_f + (size_t)p*HID))[k];
        x[4*k]=v.x; x[4*k+1]=v.y; x[4*k+2]=v.z; x[4*k+3]=v.w;
    }
    float h[HID];
    for (int hh = 0; hh < HID; ++hh) {
        float a = sb1[hh];
        const float4* wr = (const float4*)&sW1[hh*HID];
        #pragma unroll
        for (int c4 = 0; c4 < HID/4; c4++) {
            float4 wv = wr[c4];
            a = fmaf(wv.x, x[4*c4], a);   a = fmaf(wv.y, x[4*c4+1], a);
            a = fmaf(wv.z, x[4*c4+2], a); a = fmaf(wv.w, x[4*c4+3], a);
        }
        h[hh] = leaky(a);
    }
    float y[32];
    for (int hh = 0; hh < 32; ++hh) {
        float a = sb2h[hh];
        const float4* wr = (const float4*)&sW2h[hh*HID];
        #pragma unroll
        for (int c4 = 0; c4 < HID/4; c4++) {
            float4 wv = wr[c4];
            a = fmaf(wv.x, h[4*c4], a);   a = fmaf(wv.y, h[4*c4+1], a);
            a = fmaf(wv.z, h[4*c4+2], a); a = fmaf(wv.w, h[4*c4+3], a);
        }
        y[hh] = leaky(a);
    }
    #pragma unroll
    for (int k = 0; k < 8; k++)
        ((float4*)(g_pre + (size_t)p*HID + cb*32))[k] = make_float4(y[4*k], y[4*k+1], y[4*k+2], y[4*k+3]);

    float sums[2] = {0,0}, sqs[2] = {0,0};
    #pragma unroll
    for (int hh = 0; hh < 32; ++hh) { int gI = hh >> 4; sums[gI] += y[hh]; sqs[gI] += y[hh]*y[hh]; }
    red[tid][0] = sums[0]; red[tid][1] = sums[1];
    red[tid][2] = sqs[0];  red[tid][3] = sqs[1];
    __syncthreads();
    for (int st = 64; st > 0; st >>= 1) {
        if (tid < st) {
            #pragma unroll
            for (int j = 0; j < 4; j++) red[tid][j] += red[tid+st][j];
        }
        __syncthreads();
    }
    if (tid == 0) {
        g_statp_out[blockIdx.x][cb*2+0] = red[0][0];
        g_statp_out[blockIdx.x][cb*2+1] = red[0][1];
        g_statp_out[blockIdx.x][4+cb*2+0] = red[0][2];
        g_statp_out[blockIdx.x][4+cb*2+1] = red[0][3];
    }
}

// =====================================================================
extern "C" void kernel_launch(void* const* d_in, const int* in_sizes, int n_in,
                              void* d_out, int out_size)
{
    const float* points   = (const float*)d_in[0];
    const float* nuv      = (const float*)d_in[1];
    const float* features = (const float*)d_in[2];
    const float* W_in1    = (const float*)d_in[3];
    const float* b_in1    = (const float*)d_in[4];
    const float* W_in2    = (const float*)d_in[5];
    const float* b_in2    = (const float*)d_in[6];
    const float* gn_in_w  = (const float*)d_in[7];
    const float* gn_in_b  = (const float*)d_in[8];
    const float* A1       = (const float*)d_in[9];
    const float* B1       = (const float*)d_in[10];
    const float* A2       = (const float*)d_in[11];
    const float* B2       = (const float*)d_in[12];
    const float* W_out1   = (const float*)d_in[13];
    const float* b_out1   = (const float*)d_in[14];
    const float* W_out2   = (const float*)d_in[15];
    const float* b_out2   = (const float*)d_in[16];
    const float* gn_out_w = (const float*)d_in[17];
    const float* gn_out_b = (const float*)d_in[18];
    float* out = (float*)d_out;

    zero_stats_kernel<<<1, 128>>>();
    mlp_in_kernel<<<128, 128>>>(features, W_in1, b_in1, W_in2, b_in2);
    norm_kernel<<<NPTS/64, 64>>>(0, gn_in_w, gn_in_b, out);
    conv_kernel<<<dim3(NPTS/NBLK, SPLIT), 128>>>(points, nuv, A1, B1, A2, B2);
    reduce_kernel<<<NPTS*32/256, 256>>>();
    mlp_out_kernel<<<128, 128>>>(W_out1, b_out1, W_out2, b_out2);
    norm_kernel<<<NPTS/64, 64>>>(1, gn_out_w, gn_out_b, out);
}